// round 16
// baseline (speedup 1.0000x reference)
#include <cuda_runtime.h>
#include <cuda_fp16.h>
#include <math.h>
#include <stdint.h>

#define BB   16
#define TT   1024
#define DIM  500
#define KP   512
#define NROWS (BB*TT)

// ---------------- scratch ------------------------------------------------------
__device__ __half g_h[(size_t)NROWS*KP];      // col 500 == 1.0 (bias augmentation)
__device__ __half tmp_h[(size_t)NROWS*KP];
__device__ __half kw_h[KP*KP], qw_h[KP*KP];   // zero-padded fp16 K_w,Q_w
__device__ __half mt_h[KP*KP];                // Mt = Qw@Kw^T; row500 = Kw@qb
__device__ float  d_extT[KP];                 // Qw@kb | c0 | 0
__device__ __half wt_h[KP*KP];                // V_w transposed fp16
__device__ __half vt_h[(size_t)BB*KP*TT];
__device__ __half p_h[(size_t)BB*TT*TT];      // S (fp16) then P, in place
__device__ float d_part[BB*32*DIM];
__device__ float d_subj[BB*DIM], d_qv[BB*DIM], d_tw[BB*DIM], d_cv[BB*DIM], d_m[BB*DIM];
__device__ float d_klog[BB*TT], d_kw[BB*TT];

// ---------------- mma.sync helpers ----------------------------------------------
__device__ __forceinline__ uint32_t smem_u32(const void* p){
    uint32_t a;
    asm("{ .reg .u64 t; cvta.to.shared.u64 t, %1; cvt.u32.u64 %0, t; }":"=r"(a):"l"(p));
    return a;
}
__device__ __forceinline__ void ldsm4(uint32_t* r, uint32_t addr){
    asm volatile("ldmatrix.sync.aligned.m8n8.x4.shared.b16 {%0,%1,%2,%3}, [%4];"
        : "=r"(r[0]),"=r"(r[1]),"=r"(r[2]),"=r"(r[3]) : "r"(addr));
}
#define MMA(c,a,b) asm volatile( \
    "mma.sync.aligned.m16n8k16.row.col.f32.f16.f16.f32 " \
    "{%0,%1,%2,%3},{%4,%5,%6,%7},{%8,%9},{%0,%1,%2,%3};" \
    : "+f"((c)[0]),"+f"((c)[1]),"+f"((c)[2]),"+f"((c)[3]) \
    : "r"((a)[0]),"r"((a)[1]),"r"((a)[2]),"r"((a)[3]),"r"((b)[0]),"r"((b)[1]))
__device__ __forceinline__ void cpa16(uint32_t dst, const void* src){
    asm volatile("cp.async.cg.shared.global [%0], [%1], 16;"::"r"(dst),"l"(src));
}
#define CP_COMMIT() asm volatile("cp.async.commit_group;":::"memory")
#define CP_WAIT0()  asm volatile("cp.async.wait_group 0;":::"memory")
#define CP_WAIT1()  asm volatile("cp.async.wait_group 1;":::"memory")

#define SAE 72
#define TILE_B (128*SAE*2)
#define STAGE_B (2*TILE_B)
#define SMEM_DYN (3*STAGE_B)

__device__ __forceinline__ __half2 pack_h2(float a, float b){
    return __floats2half2_rn(a, b);
}

// ---- GEMM core (champion config) ----
struct GemmCore {
    uint32_t sb; int tid, lane, wid, wm, wn;
    const __half *A0, *B0; int lda, ldb;
    float acc[2][8][4];
    __device__ __forceinline__ void init(uint32_t sb_, const __half* A0_, int lda_,
                                         const __half* B0_, int ldb_){
        sb=sb_; tid=threadIdx.x; lane=tid&31; wid=tid>>5;
        wm=(wid&3)*32; wn=(wid>>2)*64;
        A0=A0_; B0=B0_; lda=lda_; ldb=ldb_;
        #pragma unroll
        for (int i=0;i<2;i++)
            #pragma unroll
            for (int j=0;j<8;j++)
                #pragma unroll
                for (int e=0;e<4;e++) acc[i][j][e]=0.f;
    }
    __device__ __forceinline__ void load_chunk(int ch, int stage){
        const __half* a = A0 + ch*64;
        const __half* b = B0 + ch*64;
        uint32_t db = sb + stage*STAGE_B;
        #pragma unroll
        for (int t=0;t<4;t++){
            int idx = tid + t*256;
            int r = idx >> 3, c = (idx & 7)*8;
            uint32_t off = (uint32_t)r*144 + c*2;
            cpa16(db + off,          a + (size_t)r*lda + c);
            cpa16(db + TILE_B + off, b + (size_t)r*ldb + c);
        }
    }
    __device__ __forceinline__ void compute(int stage){
        uint32_t ab = sb + stage*STAGE_B;
        uint32_t bb = ab + TILE_B;
        #pragma unroll
        for (int k16 = 0; k16 < 64; k16 += 16){
            uint32_t af[2][4], bf[4][4];
            int arow = wm + (lane & 7) + ((lane >> 3) & 1)*8;
            int acol = k16 + (lane >> 4)*8;
            #pragma unroll
            for (int mt=0; mt<2; mt++)
                ldsm4(af[mt], ab + (uint32_t)(arow + mt*16)*144 + acol*2);
            int brow = wn + (lane & 7) + (lane >> 4)*8;
            int bcol = k16 + ((lane >> 3) & 1)*8;
            #pragma unroll
            for (int ng=0; ng<4; ng++)
                ldsm4(bf[ng], bb + (uint32_t)(brow + ng*16)*144 + bcol*2);
            #pragma unroll
            for (int mt=0; mt<2; mt++)
                #pragma unroll
                for (int j=0; j<8; j++)
                    MMA(acc[mt][j], af[mt], &bf[j>>1][(j&1)*2]);
        }
    }
    __device__ __forceinline__ void run(int Kc){
        load_chunk(0, 0); CP_COMMIT();
        if (Kc > 1){ load_chunk(1, 1); CP_COMMIT(); }
        for (int ch = 0; ch < Kc; ch++){
            if (ch + 1 < Kc) CP_WAIT1(); else CP_WAIT0();
            __syncthreads();
            if (ch + 2 < Kc){ load_chunk(ch+2, (ch+2)%3); CP_COMMIT(); }
            compute(ch % 3);
        }
        __syncthreads();
    }
};

// EPI 3 = *ext[z] -> fp32; EPI 5 = fp16; EPI 6 = +ext[n] -> fp16
template<int EPI>
__global__ void __launch_bounds__(256)
mm_gemm(const __half* __restrict__ A, long sAz, int lda,
        const __half* __restrict__ B, long sBz, int ldb,
        float* __restrict__ C, __half* __restrict__ Ch,
        long sCz, int ldc, const float* __restrict__ ext, long sExt, int N, int Kc)
{
    extern __shared__ char sm[];
    const int z = blockIdx.z, n0 = blockIdx.x*128, m0 = blockIdx.y*128;
    GemmCore gc;
    gc.init(smem_u32(sm), A + (size_t)z*sAz + (size_t)m0*lda,
            lda, B + (size_t)z*sBz + (size_t)n0*ldb, ldb);
    gc.run(Kc);

    int g = gc.lane >> 2, tq = gc.lane & 3;
    float* Cz = C ? C + (size_t)z*sCz : (float*)0;
    __half* Chz = Ch ? Ch + (size_t)z*sCz : (__half*)0;
    #pragma unroll
    for (int mt=0; mt<2; mt++)
        #pragma unroll
        for (int j=0; j<8; j++){
            int gm = m0 + gc.wm + mt*16 + g;
            int gn = n0 + gc.wn + j*8 + tq*2;
            float* c = gc.acc[mt][j];
            if (EPI == 5 || EPI == 6){
                float b0 = (EPI==6) ? ext[gn]   : 0.f;
                float b1 = (EPI==6) ? ext[gn+1] : 0.f;
                #pragma unroll
                for (int h=0; h<2; h++){
                    int rm = gm + h*8;
                    if (gn + 1 < N)
                        *reinterpret_cast<__half2*>(Chz + (size_t)rm*ldc + gn) =
                            pack_h2(c[h*2+0]+b0, c[h*2+1]+b1);
                }
            } else {
                #pragma unroll
                for (int e=0; e<4; e++){
                    int rm = gm + (e >> 1)*8;
                    int rn = gn + (e & 1);
                    if (rn >= N) continue;
                    float v = c[e];
                    size_t idx = (size_t)rm*ldc + rn;
                    if (EPI == 3) Cz[idx] = v * ext[(size_t)z*sExt + rn];
                    else          Cz[idx] = v;
                }
            }
        }
}

// ---------------- V projection with transposed fp16 output (vt) -------------------
__global__ void __launch_bounds__(256)
mm_projV(const __half* __restrict__ G, const __half* __restrict__ Wt,
         const float* __restrict__ Vb, __half* __restrict__ Vt)
{
    extern __shared__ char sm[];
    const int n0 = blockIdx.x*128, m0 = blockIdx.y*128;
    GemmCore gc;
    gc.init(smem_u32(sm), G + (size_t)m0*KP, KP, Wt + (size_t)n0*KP, KP);
    gc.run(8);

    int g = gc.lane >> 2, tq = gc.lane & 3;
    float* fs = (float*)sm;
    #pragma unroll
    for (int mt=0; mt<2; mt++)
        #pragma unroll
        for (int j=0; j<8; j++){
            int rml = gc.wm + mt*16 + g;
            int rnl = gc.wn + j*8 + tq*2;
            float* c = gc.acc[mt][j];
            #pragma unroll
            for (int e=0; e<4; e++)
                fs[(rml + (e>>1)*8)*129 + rnl + (e&1)] = c[e];
        }
    __syncthreads();
    for (int it = gc.tid; it < 16384; it += 256){
        int jl = it >> 7, ml = it & 127;
        int gn = n0 + jl;
        if (gn >= DIM) continue;
        int gm = m0 + ml;
        float v = fs[ml*129 + jl] + Vb[gn];
        Vt[(size_t)(gm>>10)*KP*TT + (size_t)gn*TT + (gm & 1023)] = __float2half(v);
    }
}

// ---------------- small kernels ----------------------------------------------------
__global__ void buildsplit_g_kernel(
    const int* __restrict__ words, const int* __restrict__ pos,
    const int* __restrict__ ner, const int* __restrict__ chunks,
    const int* __restrict__ subj_pos, const int* __restrict__ obj_pos,
    const int* __restrict__ on_path, const float* __restrict__ dep_feat,
    const float* __restrict__ emb_w, const float* __restrict__ pos_w,
    const float* __restrict__ ner_w, const float* __restrict__ chunk_w,
    const float* __restrict__ position_w)
{
    int row = blockIdx.x, d = threadIdx.x;   // 512 threads
    float v = 0.f;
    if (d < 300)       v = emb_w[(size_t)words[row]*300 + d];
    else if (d < 335)  v = pos_w[pos[row]*35 + (d-300)];
    else if (d < 365)  v = ner_w[ner[row]*30 + (d-335)];
    else if (d < 395)  v = chunk_w[chunks[row]*30 + (d-365)];
    else if (d < 425)  v = position_w[subj_pos[row]*30 + (d-395)];
    else if (d < 455)  v = position_w[obj_pos[row]*30 + (d-425)];
    else if (d == 455) v = (float)on_path[row];
    else if (d < DIM)  v = dep_feat[(size_t)row*44 + (d-456)];
    else if (d == DIM) v = 1.0f;
    g_h[(size_t)row*KP + d] = __float2half(v);
}
__global__ void kwqw_copy(const float* __restrict__ Kw, const float* __restrict__ Qw){
    int i = blockIdx.x, j = threadIdx.x;
    bool in = (j < DIM);
    kw_h[i*KP+j] = __float2half(in ? Kw[(size_t)i*DIM+j] : 0.f);
    qw_h[i*KP+j] = __float2half(in ? Qw[(size_t)i*DIM+j] : 0.f);
}
__global__ void vecfast(const float* __restrict__ Kw, const float* __restrict__ Qw,
                        const float* __restrict__ kb, const float* __restrict__ qb){
    int side = blockIdx.y;
    int j = blockIdx.x*8 + (threadIdx.x>>5);
    int lane = threadIdx.x & 31;
    float s = 0.f;
    if (j < DIM){
        const float* Wr = (side==0) ? (Kw + (size_t)j*DIM) : (Qw + (size_t)j*DIM);
        const float* vv = (side==0) ? qb : kb;
        for (int t=lane; t<DIM; t+=32) s = fmaf(Wr[t], vv[t], s);
    } else if (j == DIM && side == 1){
        for (int t=lane; t<DIM; t+=32) s = fmaf(kb[t], qb[t], s);
    }
    #pragma unroll
    for (int o=16;o;o>>=1) s += __shfl_xor_sync(0xffffffffu, s, o);
    if (lane == 0){
        if (side == 0) mt_h[500*KP + j] = __float2half(j < DIM ? s : 0.f);
        else           d_extT[j] = (j <= DIM) ? s : 0.f;
    }
}
__global__ void wtransV_kernel(const float* __restrict__ W){
    __shared__ float tile[32][33];
    int x0 = blockIdx.x*32, y0 = blockIdx.y*32;
    int tx = threadIdx.x, ty = threadIdx.y;
    #pragma unroll
    for (int i=0;i<4;i++){ int k=x0+ty+i*8, n=y0+tx;
        tile[ty+i*8][tx] = (k<DIM && n<DIM) ? W[(size_t)k*DIM+n] : 0.f; }
    __syncthreads();
    #pragma unroll
    for (int i=0;i<4;i++){ int n=y0+ty+i*8, k=x0+tx;
        wt_h[(size_t)n*KP + k] = __float2half(tile[tx][ty+i*8]); }
}
__global__ void subj_partial_kernel(const int* __restrict__ subj_pos){
    int b = blockIdx.x, ch = blockIdx.y, d = threadIdx.x;
    if (d >= DIM) return;
    float mx = -3.4e38f;
    int base = b*TT + ch*32;
    for (int i=0;i<32;i++){ int row=base+i;
        float v = (subj_pos[row]!=0) ? -1.0e12f : __half2float(g_h[(size_t)row*KP+d]);
        mx = fmaxf(mx,v); }
    d_part[(b*32+ch)*DIM+d] = mx;
}
__global__ void subj_reduce_kernel(){
    int b = blockIdx.x, d = threadIdx.x; if (d>=DIM) return;
    float mx = d_part[(b*32)*DIM+d];
    #pragma unroll
    for (int c=1;c<32;c++) mx = fmaxf(mx, d_part[(b*32+c)*DIM+d]);
    d_subj[b*DIM+d] = mx;
}
__global__ void dense_q2(const float* __restrict__ W, const float* __restrict__ bias){
    int b=blockIdx.x, jc=blockIdx.y, w=threadIdx.x>>5, lane=threadIdx.x&31, j=jc*32+lane;
    __shared__ float s[DIM]; __shared__ float red[8][32];
    for (int d=threadIdx.x; d<DIM; d+=256) s[d]=d_subj[b*DIM+d];
    __syncthreads();
    float acc=0.f;
    if (j<DIM) for (int d=w; d<DIM; d+=8)
        acc = fmaf(s[d], W[(size_t)d*DIM+j] + W[(size_t)(d+DIM)*DIM+j], acc);
    red[w][lane]=acc; __syncthreads();
    if (w==0 && j<DIM){ float t=0.f;
        #pragma unroll
        for (int k=0;k<8;k++) t+=red[k][lane];
        d_qv[b*DIM+j]=fmaxf(t+bias[j],0.f); }
}
__global__ void dense_t2(const float* __restrict__ W, const float* __restrict__ bias,
                         const float* __restrict__ Wk){
    int b=blockIdx.x, jc=blockIdx.y, w=threadIdx.x>>5, lane=threadIdx.x&31, j=jc*32+lane;
    __shared__ float s[DIM]; __shared__ float red[8][32];
    for (int d=threadIdx.x; d<DIM; d+=256) s[d]=d_qv[b*DIM+d];
    __syncthreads();
    float acc=0.f;
    if (j<DIM) for (int d=w; d<DIM; d+=8) acc = fmaf(s[d], W[(size_t)d*DIM+j], acc);
    red[w][lane]=acc; __syncthreads();
    if (w==0 && j<DIM){ float t=0.f;
        #pragma unroll
        for (int k=0;k<8;k++) t+=red[k][lane];
        d_tw[b*DIM+j]=fmaxf(t+bias[j],0.f)*Wk[j]; }
}
__global__ void dense_m2(const float* __restrict__ W, const float* __restrict__ bias){
    int b=blockIdx.x, jc=blockIdx.y, w=threadIdx.x>>5, lane=threadIdx.x&31, j=jc*32+lane;
    __shared__ float sc[DIM], ss[DIM]; __shared__ float red[8][32];
    for (int d=threadIdx.x; d<DIM; d+=256){ sc[d]=d_cv[b*DIM+d]; ss[d]=d_subj[b*DIM+d]; }
    __syncthreads();
    float acc=0.f;
    if (j<DIM) for (int d=w; d<DIM; d+=8){
        acc = fmaf(sc[d], W[(size_t)d*DIM+j], acc);
        acc = fmaf(ss[d], W[(size_t)(DIM+d)*DIM+j] + W[(size_t)(2*DIM+d)*DIM+j], acc); }
    red[w][lane]=acc; __syncthreads();
    if (w==0 && j<DIM){ float t=0.f;
        #pragma unroll
        for (int k=0;k<8;k++) t+=red[k][lane];
        d_m[b*DIM+j]=fmaxf(t+bias[j],0.f); }
}
__device__ __forceinline__ float warpSum(float v){
    #pragma unroll
    for (int o=16;o;o>>=1) v += __shfl_xor_sync(0xffffffffu,v,o);
    return v;
}
__global__ void klogit_kernel(const float* __restrict__ Wk_b){
    int row = blockIdx.x, b = row>>10, tid = threadIdx.x;
    const __half* gr = g_h + (size_t)row*KP;
    const float* tw = d_tw + b*DIM;
    float s = 0.f;
    for (int d=tid; d<DIM; d+=128) s = fmaf(__half2float(gr[d]), tw[d], s);
    s = warpSum(s);
    __shared__ float sm[4];
    if ((tid&31)==0) sm[tid>>5]=s;
    __syncthreads();
    if (tid==0) d_klog[row]=sm[0]+sm[1]+sm[2]+sm[3]+Wk_b[0];
}
__global__ void softmax_k_kernel(){
    int b=blockIdx.x, tid=threadIdx.x;
    __shared__ float red[256];
    const float* kr = d_klog + b*TT;
    float lmax=-3.4e38f;
    for (int t=tid;t<TT;t+=256) lmax=fmaxf(lmax,kr[t]);
    red[tid]=lmax; __syncthreads();
    for (int s=128;s;s>>=1){ if(tid<s) red[tid]=fmaxf(red[tid],red[tid+s]); __syncthreads(); }
    float m=red[0]; __syncthreads();
    float ls=0.f;
    for (int t=tid;t<TT;t+=256) ls+=__expf(kr[t]-m);
    red[tid]=ls; __syncthreads();
    for (int s=128;s;s>>=1){ if(tid<s) red[tid]+=red[tid+s]; __syncthreads(); }
    float inv=1.f/red[0];
    for (int t=tid;t<TT;t+=256) d_kw[b*TT+t]=__expf(kr[t]-m)*inv;
}
__global__ void c_partial_kernel(){
    int b=blockIdx.x, ch=blockIdx.y, d=threadIdx.x; if (d>=DIM) return;
    float s=0.f;
    int base=b*TT+ch*32;
    for (int i=0;i<32;i++){ int row=base+i;
        s=fmaf(d_kw[row], __half2float(g_h[(size_t)row*KP+d]), s); }
    d_part[(b*32+ch)*DIM+d]=s;
}
__global__ void c_reduce_kernel(){
    int b=blockIdx.x, d=threadIdx.x; if (d>=DIM) return;
    float s=0.f;
    #pragma unroll
    for (int c=0;c<32;c++) s+=d_part[(b*32+c)*DIM+d];
    d_cv[b*DIM+d]=s;
}
__global__ void softmax_S_kernel(float* __restrict__ att){
    int row = blockIdx.x;
    int t = row & (TT-1);
    int tid = threadIdx.x;
    int w = tid>>5, lane = tid&31;
    __shared__ float srow[TT];
    __shared__ float red1[8]; __shared__ float red2[8];
    __shared__ float bc[2];
    __half2* Pr2 = reinterpret_cast<__half2*>(p_h + (size_t)row*TT);
    const float invs = 1.f/sqrtf(500.f);
    float s1=0.f, s2=0.f;
    for (int s=tid;s<TT/2;s+=256){
        float2 v = __half22float2(Pr2[s]);
        s1 += __expf(v.x) + __expf(v.y);
        float e0 = __expf(v.x*invs), e1 = __expf(v.y*invs);
        srow[2*s]=e0; srow[2*s+1]=e1;
        s2 += e0 + e1;
    }
    s1 = warpSum(s1); s2 = warpSum(s2);
    if (lane==0){ red1[w]=s1; red2[w]=s2; }
    __syncthreads();
    if (tid==0){
        float S1=0.f, S2=0.f;
        #pragma unroll
        for (int k=0;k<8;k++){ S1+=red1[k]; S2+=red2[k]; }
        bc[0]=S1; bc[1]=S2;
    }
    __syncthreads();
    float S1=bc[0], S2=bc[1];
    if (tid==0){
        float sd = __half2float(p_h[(size_t)row*TT+t]);
        att[row]=(1.f-__expf(sd)/S1)*invs;
    }
    float invZ2=1.f/S2;
    for (int s=tid;s<TT/2;s+=256)
        Pr2[s]=pack_h2(srow[2*s]*invZ2, srow[2*s+1]*invZ2);
}

// ---------------- streams ------------------------------------------------------------
struct StreamBundle {
    cudaStream_t s2, s3;
    cudaEvent_t eFork0, eG, eJoin, eM, eV;
    StreamBundle(){
        cudaStreamCreateWithFlags(&s2, cudaStreamNonBlocking);
        cudaStreamCreateWithFlags(&s3, cudaStreamNonBlocking);
        cudaEventCreateWithFlags(&eFork0, cudaEventDisableTiming);
        cudaEventCreateWithFlags(&eG,   cudaEventDisableTiming);
        cudaEventCreateWithFlags(&eJoin,cudaEventDisableTiming);
        cudaEventCreateWithFlags(&eM,   cudaEventDisableTiming);
        cudaEventCreateWithFlags(&eV,   cudaEventDisableTiming);
    }
};
static StreamBundle g_sb;

// ---------------- launch -------------------------------------------------------------
extern "C" void kernel_launch(void* const* d_in, const int* in_sizes, int n_in,
                              void* d_out, int out_size)
{
    const int* words=(const int*)d_in[0];
    const int* pos=(const int*)d_in[2];
    const int* ner=(const int*)d_in[3];
    const int* subj_pos=(const int*)d_in[4];
    const int* obj_pos=(const int*)d_in[5];
    const int* chunks=(const int*)d_in[6];
    const int* on_path=(const int*)d_in[7];
    const float* dep_feat=(const float*)d_in[8];
    const float* emb_w=(const float*)d_in[9];
    const float* pos_w=(const float*)d_in[10];
    const float* ner_w=(const float*)d_in[11];
    const float* chunk_w=(const float*)d_in[12];
    const float* position_w=(const float*)d_in[13];
    const float* Wq_w=(const float*)d_in[14]; const float* Wq_b=(const float*)d_in[15];
    const float* Wc_w=(const float*)d_in[16]; const float* Wc_b=(const float*)d_in[17];
    const float* Wk_w=(const float*)d_in[18]; const float* Wk_b=(const float*)d_in[19];
    const float* Wm_w=(const float*)d_in[20]; const float* Wm_b=(const float*)d_in[21];
    const float* K_w=(const float*)d_in[22];  const float* K_b=(const float*)d_in[23];
    const float* Q_w=(const float*)d_in[24];  const float* Q_b=(const float*)d_in[25];
    const float* V_w=(const float*)d_in[26];  const float* V_b=(const float*)d_in[27];

    float* out = (float*)d_out;
    float* att = out + (size_t)NROWS*DIM;

    float *mp, *extp;
    __half *ghp,*tmpp,*kwp,*qwp,*mtp,*wthp,*vthp,*php;
    cudaGetSymbolAddress((void**)&mp, d_m);
    cudaGetSymbolAddress((void**)&extp, d_extT);
    cudaGetSymbolAddress((void**)&ghp, g_h);
    cudaGetSymbolAddress((void**)&tmpp, tmp_h);
    cudaGetSymbolAddress((void**)&kwp, kw_h);
    cudaGetSymbolAddress((void**)&qwp, qw_h);
    cudaGetSymbolAddress((void**)&mtp, mt_h);
    cudaGetSymbolAddress((void**)&wthp, wt_h);
    cudaGetSymbolAddress((void**)&vthp, vt_h);
    cudaGetSymbolAddress((void**)&php, p_h);

    cudaFuncSetAttribute(mm_gemm<3>, cudaFuncAttributeMaxDynamicSharedMemorySize, SMEM_DYN);
    cudaFuncSetAttribute(mm_gemm<5>, cudaFuncAttributeMaxDynamicSharedMemorySize, SMEM_DYN);
    cudaFuncSetAttribute(mm_gemm<6>, cudaFuncAttributeMaxDynamicSharedMemorySize, SMEM_DYN);
    cudaFuncSetAttribute(mm_projV,   cudaFuncAttributeMaxDynamicSharedMemorySize, SMEM_DYN);

    cudaStream_t s2 = g_sb.s2, s3 = g_sb.s3;

    // legal fork: record event on origin stream as first node (R10-proven)
    cudaEventRecord(g_sb.eFork0, 0);
    cudaStreamWaitEvent(s2, g_sb.eFork0, 0);
    cudaStreamWaitEvent(s3, g_sb.eFork0, 0);

    // s2: precompute chain (weights-only; concurrent with buildsplit)
    kwqw_copy<<<DIM, 512, 0, s2>>>(K_w, Q_w);
    mm_gemm<5><<<dim3(4,4,1), 256, SMEM_DYN, s2>>>(qwp, 0, KP, kwp, 0, KP,
        nullptr, mtp, 0, KP, nullptr, 0, KP, 8);
    vecfast<<<dim3(64,2), 256, 0, s2>>>(K_w, Q_w, K_b, Q_b);
    wtransV_kernel<<<dim3(16,16), dim3(32,8), 0, s2>>>(V_w);
    cudaEventRecord(g_sb.eM, s2);    // mt, extT, wt all ready

    // stream 0: fused embedding -> fp16 g_h
    buildsplit_g_kernel<<<NROWS, 512>>>(words, pos, ner, chunks, subj_pos, obj_pos,
        on_path, dep_feat, emb_w, pos_w, ner_w, chunk_w, position_w);
    cudaEventRecord(g_sb.eG, 0);

    // side chain on s2 (consumes g_h, produces d_m)
    cudaStreamWaitEvent(s2, g_sb.eG, 0);
    subj_partial_kernel<<<dim3(BB,32), 512, 0, s2>>>(subj_pos);
    subj_reduce_kernel<<<BB, 512, 0, s2>>>();
    dense_q2<<<dim3(BB,16), 256, 0, s2>>>(Wq_w, Wq_b);
    dense_t2<<<dim3(BB,16), 256, 0, s2>>>(Wc_w, Wc_b, Wk_w);
    klogit_kernel<<<NROWS, 128, 0, s2>>>(Wk_b);
    softmax_k_kernel<<<BB, 256, 0, s2>>>();
    c_partial_kernel<<<dim3(BB,32), 512, 0, s2>>>();
    c_reduce_kernel<<<BB, 512, 0, s2>>>();
    dense_m2<<<dim3(BB,16), 256, 0, s2>>>(Wm_w, Wm_b);
    cudaEventRecord(g_sb.eJoin, s2);

    // s3: V projection (needs wt from eM + g from eG); fills softmax bubble
    cudaStreamWaitEvent(s3, g_sb.eM, 0);
    cudaStreamWaitEvent(s3, g_sb.eG, 0);
    mm_projV<<<dim3(4,128), 256, SMEM_DYN, s3>>>(ghp, wthp, V_b, vthp);
    cudaEventRecord(g_sb.eV, s3);

    // stream 0: tmp = g @ Mt^T + extT (needs eM)
    cudaStreamWaitEvent(0, g_sb.eM, 0);
    mm_gemm<6><<<dim3(4,128,1), 256, SMEM_DYN>>>(ghp, 0, KP, mtp, 0, KP,
        nullptr, tmpp, 0, KP, extp, 0, KP, 8);

    // S = tmp @ g^T -> fp16 into p_h
    mm_gemm<5><<<dim3(8,8,BB), 256, SMEM_DYN>>>(tmpp, (long)TT*KP, KP, ghp, (long)TT*KP, KP,
        nullptr, php, (long)TT*TT, TT, nullptr, 0, TT, 8);

    softmax_S_kernel<<<NROWS, 256>>>(att);

    // join + final GEMM: out = P @ vt^T, *m
    cudaStreamWaitEvent(0, g_sb.eJoin, 0);
    cudaStreamWaitEvent(0, g_sb.eV, 0);
    mm_gemm<3><<<dim3(4,8,BB), 256, SMEM_DYN>>>(php, (long)TT*TT, TT, vthp, (long)KP*TT, TT,
        out, nullptr, (long)TT*DIM, DIM, mp, DIM, DIM, 16);
}

// round 17
// speedup vs baseline: 1.1243x; 1.1243x over previous
#include <cuda_runtime.h>
#include <cuda_fp16.h>
#include <math.h>
#include <stdint.h>

#define BB   16
#define TT   1024
#define DIM  500
#define KP   512
#define NROWS (BB*TT)

// ---------------- scratch ------------------------------------------------------
__device__ __half g_h[(size_t)NROWS*KP];      // col 500 == 1.0 (bias augmentation)
__device__ __half tmp_h[(size_t)NROWS*KP];
__device__ __half kw_h[KP*KP], qw_h[KP*KP];   // zero-padded fp16 K_w,Q_w
__device__ __half mt_h[KP*KP];                // Mt = Qw@Kw^T; row500 = Kw@qb
__device__ float  d_extT[KP];                 // Qw@kb | c0 | 0
__device__ __half wt_h[KP*KP];                // V_w transposed fp16
__device__ __half vt_h[(size_t)BB*KP*TT];
__device__ __half p_h[(size_t)BB*TT*TT];      // S (fp16) then P, in place
__device__ float d_part[BB*32*DIM];
__device__ float d_subj[BB*DIM], d_qv[BB*DIM], d_tw[BB*DIM], d_cv[BB*DIM], d_m[BB*DIM];
__device__ float d_klog[BB*TT], d_kw[BB*TT];

// ---------------- mma.sync helpers ----------------------------------------------
__device__ __forceinline__ uint32_t smem_u32(const void* p){
    uint32_t a;
    asm("{ .reg .u64 t; cvta.to.shared.u64 t, %1; cvt.u32.u64 %0, t; }":"=r"(a):"l"(p));
    return a;
}
__device__ __forceinline__ void ldsm4(uint32_t* r, uint32_t addr){
    asm volatile("ldmatrix.sync.aligned.m8n8.x4.shared.b16 {%0,%1,%2,%3}, [%4];"
        : "=r"(r[0]),"=r"(r[1]),"=r"(r[2]),"=r"(r[3]) : "r"(addr));
}
#define MMA(c,a,b) asm volatile( \
    "mma.sync.aligned.m16n8k16.row.col.f32.f16.f16.f32 " \
    "{%0,%1,%2,%3},{%4,%5,%6,%7},{%8,%9},{%0,%1,%2,%3};" \
    : "+f"((c)[0]),"+f"((c)[1]),"+f"((c)[2]),"+f"((c)[3]) \
    : "r"((a)[0]),"r"((a)[1]),"r"((a)[2]),"r"((a)[3]),"r"((b)[0]),"r"((b)[1]))
__device__ __forceinline__ void cpa16(uint32_t dst, const void* src){
    asm volatile("cp.async.cg.shared.global [%0], [%1], 16;"::"r"(dst),"l"(src));
}
#define CP_COMMIT() asm volatile("cp.async.commit_group;":::"memory")
#define CP_WAIT0()  asm volatile("cp.async.wait_group 0;":::"memory")
#define CP_WAIT1()  asm volatile("cp.async.wait_group 1;":::"memory")

#define SAE 72
#define TILE_B (128*SAE*2)
#define STAGE_B (2*TILE_B)
#define SMEM_DYN (3*STAGE_B)

__device__ __forceinline__ __half2 pack_h2(float a, float b){
    return __floats2half2_rn(a, b);
}

// ---- GEMM core (champion config: 256 thr, 32x64 warp tiles, 3-stage, 1 barrier) ----
struct GemmCore {
    uint32_t sb; int tid, lane, wid, wm, wn;
    const __half *A0, *B0; int lda, ldb;
    float acc[2][8][4];
    __device__ __forceinline__ void init(uint32_t sb_, const __half* A0_, int lda_,
                                         const __half* B0_, int ldb_){
        sb=sb_; tid=threadIdx.x; lane=tid&31; wid=tid>>5;
        wm=(wid&3)*32; wn=(wid>>2)*64;
        A0=A0_; B0=B0_; lda=lda_; ldb=ldb_;
        #pragma unroll
        for (int i=0;i<2;i++)
            #pragma unroll
            for (int j=0;j<8;j++)
                #pragma unroll
                for (int e=0;e<4;e++) acc[i][j][e]=0.f;
    }
    __device__ __forceinline__ void load_chunk(int ch, int stage){
        const __half* a = A0 + ch*64;
        const __half* b = B0 + ch*64;
        uint32_t db = sb + stage*STAGE_B;
        #pragma unroll
        for (int t=0;t<4;t++){
            int idx = tid + t*256;
            int r = idx >> 3, c = (idx & 7)*8;
            uint32_t off = (uint32_t)r*144 + c*2;
            cpa16(db + off,          a + (size_t)r*lda + c);
            cpa16(db + TILE_B + off, b + (size_t)r*ldb + c);
        }
    }
    __device__ __forceinline__ void compute(int stage){
        uint32_t ab = sb + stage*STAGE_B;
        uint32_t bb = ab + TILE_B;
        #pragma unroll
        for (int k16 = 0; k16 < 64; k16 += 16){
            uint32_t af[2][4], bf[4][4];
            int arow = wm + (lane & 7) + ((lane >> 3) & 1)*8;
            int acol = k16 + (lane >> 4)*8;
            #pragma unroll
            for (int mt=0; mt<2; mt++)
                ldsm4(af[mt], ab + (uint32_t)(arow + mt*16)*144 + acol*2);
            int brow = wn + (lane & 7) + (lane >> 4)*8;
            int bcol = k16 + ((lane >> 3) & 1)*8;
            #pragma unroll
            for (int ng=0; ng<4; ng++)
                ldsm4(bf[ng], bb + (uint32_t)(brow + ng*16)*144 + bcol*2);
            #pragma unroll
            for (int mt=0; mt<2; mt++)
                #pragma unroll
                for (int j=0; j<8; j++)
                    MMA(acc[mt][j], af[mt], &bf[j>>1][(j&1)*2]);
        }
    }
    __device__ __forceinline__ void run(int Kc){
        load_chunk(0, 0); CP_COMMIT();
        if (Kc > 1){ load_chunk(1, 1); CP_COMMIT(); }
        for (int ch = 0; ch < Kc; ch++){
            if (ch + 1 < Kc) CP_WAIT1(); else CP_WAIT0();
            __syncthreads();
            if (ch + 2 < Kc){ load_chunk(ch+2, (ch+2)%3); CP_COMMIT(); }
            compute(ch % 3);
        }
        __syncthreads();
    }
};

// EPI 3 = *ext[z] -> fp32 (float2 paired stores); EPI 5 = fp16; EPI 6 = +ext[n] -> fp16
template<int EPI>
__global__ void __launch_bounds__(256)
mm_gemm(const __half* __restrict__ A, long sAz, int lda,
        const __half* __restrict__ B, long sBz, int ldb,
        float* __restrict__ C, __half* __restrict__ Ch,
        long sCz, int ldc, const float* __restrict__ ext, long sExt, int N, int Kc)
{
    extern __shared__ char sm[];
    const int z = blockIdx.z, n0 = blockIdx.x*128, m0 = blockIdx.y*128;
    GemmCore gc;
    gc.init(smem_u32(sm), A + (size_t)z*sAz + (size_t)m0*lda,
            lda, B + (size_t)z*sBz + (size_t)n0*ldb, ldb);
    gc.run(Kc);

    int g = gc.lane >> 2, tq = gc.lane & 3;
    float* Cz = C ? C + (size_t)z*sCz : (float*)0;
    __half* Chz = Ch ? Ch + (size_t)z*sCz : (__half*)0;
    #pragma unroll
    for (int mt=0; mt<2; mt++)
        #pragma unroll
        for (int j=0; j<8; j++){
            int gm = m0 + gc.wm + mt*16 + g;
            int gn = n0 + gc.wn + j*8 + tq*2;
            float* c = gc.acc[mt][j];
            if (EPI == 5 || EPI == 6){
                float b0 = (EPI==6) ? ext[gn]   : 0.f;
                float b1 = (EPI==6) ? ext[gn+1] : 0.f;
                #pragma unroll
                for (int h=0; h<2; h++){
                    int rm = gm + h*8;
                    if (gn + 1 < N)
                        *reinterpret_cast<__half2*>(Chz + (size_t)rm*ldc + gn) =
                            pack_h2(c[h*2+0]+b0, c[h*2+1]+b1);
                }
            } else if (EPI == 3){
                if (gn + 1 < N){
                    float e0 = ext[(size_t)z*sExt + gn];
                    float e1 = ext[(size_t)z*sExt + gn + 1];
                    #pragma unroll
                    for (int h=0; h<2; h++){
                        int rm = gm + h*8;
                        float2 v2 = make_float2(c[h*2+0]*e0, c[h*2+1]*e1);
                        *reinterpret_cast<float2*>(Cz + (size_t)rm*ldc + gn) = v2;
                    }
                }
            } else {
                #pragma unroll
                for (int e=0; e<4; e++){
                    int rm = gm + (e >> 1)*8;
                    int rn = gn + (e & 1);
                    if (rn >= N) continue;
                    Cz[(size_t)rm*ldc + rn] = c[e];
                }
            }
        }
}

// ---------------- V projection with transposed fp16 output (vt) -------------------
__global__ void __launch_bounds__(256)
mm_projV(const __half* __restrict__ G, const __half* __restrict__ Wt,
         const float* __restrict__ Vb, __half* __restrict__ Vt)
{
    extern __shared__ char sm[];
    const int n0 = blockIdx.x*128, m0 = blockIdx.y*128;
    GemmCore gc;
    gc.init(smem_u32(sm), G + (size_t)m0*KP, KP, Wt + (size_t)n0*KP, KP);
    gc.run(8);

    int g = gc.lane >> 2, tq = gc.lane & 3;
    float* fs = (float*)sm;
    #pragma unroll
    for (int mt=0; mt<2; mt++)
        #pragma unroll
        for (int j=0; j<8; j++){
            int rml = gc.wm + mt*16 + g;
            int rnl = gc.wn + j*8 + tq*2;
            float* c = gc.acc[mt][j];
            #pragma unroll
            for (int e=0; e<4; e++)
                fs[(rml + (e>>1)*8)*129 + rnl + (e&1)] = c[e];
        }
    __syncthreads();
    for (int it = gc.tid; it < 16384; it += 256){
        int jl = it >> 7, ml = it & 127;
        int gn = n0 + jl;
        if (gn >= DIM) continue;
        int gm = m0 + ml;
        float v = fs[ml*129 + jl] + Vb[gn];
        Vt[(size_t)(gm>>10)*KP*TT + (size_t)gn*TT + (gm & 1023)] = __float2half(v);
    }
}

// ---------------- small kernels ----------------------------------------------------
__global__ void buildsplit_g_kernel(
    const int* __restrict__ words, const int* __restrict__ pos,
    const int* __restrict__ ner, const int* __restrict__ chunks,
    const int* __restrict__ subj_pos, const int* __restrict__ obj_pos,
    const int* __restrict__ on_path, const float* __restrict__ dep_feat,
    const float* __restrict__ emb_w, const float* __restrict__ pos_w,
    const float* __restrict__ ner_w, const float* __restrict__ chunk_w,
    const float* __restrict__ position_w)
{
    int row = blockIdx.x, d = threadIdx.x;   // 512 threads
    float v = 0.f;
    if (d < 300)       v = emb_w[(size_t)words[row]*300 + d];
    else if (d < 335)  v = pos_w[pos[row]*35 + (d-300)];
    else if (d < 365)  v = ner_w[ner[row]*30 + (d-335)];
    else if (d < 395)  v = chunk_w[chunks[row]*30 + (d-365)];
    else if (d < 425)  v = position_w[subj_pos[row]*30 + (d-395)];
    else if (d < 455)  v = position_w[obj_pos[row]*30 + (d-425)];
    else if (d == 455) v = (float)on_path[row];
    else if (d < DIM)  v = dep_feat[(size_t)row*44 + (d-456)];
    else if (d == DIM) v = 1.0f;
    g_h[(size_t)row*KP + d] = __float2half(v);
}
__global__ void kwqw_copy(const float* __restrict__ Kw, const float* __restrict__ Qw){
    int i = blockIdx.x, j = threadIdx.x;
    bool in = (j < DIM);
    kw_h[i*KP+j] = __float2half(in ? Kw[(size_t)i*DIM+j] : 0.f);
    qw_h[i*KP+j] = __float2half(in ? Qw[(size_t)i*DIM+j] : 0.f);
}
__global__ void vecfast(const float* __restrict__ Kw, const float* __restrict__ Qw,
                        const float* __restrict__ kb, const float* __restrict__ qb){
    int side = blockIdx.y;
    int j = blockIdx.x*8 + (threadIdx.x>>5);
    int lane = threadIdx.x & 31;
    float s = 0.f;
    if (j < DIM){
        const float* Wr = (side==0) ? (Kw + (size_t)j*DIM) : (Qw + (size_t)j*DIM);
        const float* vv = (side==0) ? qb : kb;
        for (int t=lane; t<DIM; t+=32) s = fmaf(Wr[t], vv[t], s);
    } else if (j == DIM && side == 1){
        for (int t=lane; t<DIM; t+=32) s = fmaf(kb[t], qb[t], s);
    }
    #pragma unroll
    for (int o=16;o;o>>=1) s += __shfl_xor_sync(0xffffffffu, s, o);
    if (lane == 0){
        if (side == 0) mt_h[500*KP + j] = __float2half(j < DIM ? s : 0.f);
        else           d_extT[j] = (j <= DIM) ? s : 0.f;
    }
}
__global__ void wtransV_kernel(const float* __restrict__ W){
    __shared__ float tile[32][33];
    int x0 = blockIdx.x*32, y0 = blockIdx.y*32;
    int tx = threadIdx.x, ty = threadIdx.y;
    #pragma unroll
    for (int i=0;i<4;i++){ int k=x0+ty+i*8, n=y0+tx;
        tile[ty+i*8][tx] = (k<DIM && n<DIM) ? W[(size_t)k*DIM+n] : 0.f; }
    __syncthreads();
    #pragma unroll
    for (int i=0;i<4;i++){ int n=y0+ty+i*8, k=x0+tx;
        wt_h[(size_t)n*KP + k] = __float2half(tile[tx][ty+i*8]); }
}
__global__ void subj_partial_kernel(const int* __restrict__ subj_pos){
    int b = blockIdx.x, ch = blockIdx.y, d = threadIdx.x;
    if (d >= DIM) return;
    float mx = -3.4e38f;
    int base = b*TT + ch*32;
    for (int i=0;i<32;i++){ int row=base+i;
        float v = (subj_pos[row]!=0) ? -1.0e12f : __half2float(g_h[(size_t)row*KP+d]);
        mx = fmaxf(mx,v); }
    d_part[(b*32+ch)*DIM+d] = mx;
}
__global__ void subj_reduce_kernel(){
    int b = blockIdx.x, d = threadIdx.x; if (d>=DIM) return;
    float mx = d_part[(b*32)*DIM+d];
    #pragma unroll
    for (int c=1;c<32;c++) mx = fmaxf(mx, d_part[(b*32+c)*DIM+d]);
    d_subj[b*DIM+d] = mx;
}
__global__ void dense_q2(const float* __restrict__ W, const float* __restrict__ bias){
    int b=blockIdx.x, jc=blockIdx.y, w=threadIdx.x>>5, lane=threadIdx.x&31, j=jc*32+lane;
    __shared__ float s[DIM]; __shared__ float red[8][32];
    for (int d=threadIdx.x; d<DIM; d+=256) s[d]=d_subj[b*DIM+d];
    __syncthreads();
    float acc=0.f;
    if (j<DIM) for (int d=w; d<DIM; d+=8)
        acc = fmaf(s[d], W[(size_t)d*DIM+j] + W[(size_t)(d+DIM)*DIM+j], acc);
    red[w][lane]=acc; __syncthreads();
    if (w==0 && j<DIM){ float t=0.f;
        #pragma unroll
        for (int k=0;k<8;k++) t+=red[k][lane];
        d_qv[b*DIM+j]=fmaxf(t+bias[j],0.f); }
}
__global__ void dense_t2(const float* __restrict__ W, const float* __restrict__ bias,
                         const float* __restrict__ Wk){
    int b=blockIdx.x, jc=blockIdx.y, w=threadIdx.x>>5, lane=threadIdx.x&31, j=jc*32+lane;
    __shared__ float s[DIM]; __shared__ float red[8][32];
    for (int d=threadIdx.x; d<DIM; d+=256) s[d]=d_qv[b*DIM+d];
    __syncthreads();
    float acc=0.f;
    if (j<DIM) for (int d=w; d<DIM; d+=8) acc = fmaf(s[d], W[(size_t)d*DIM+j], acc);
    red[w][lane]=acc; __syncthreads();
    if (w==0 && j<DIM){ float t=0.f;
        #pragma unroll
        for (int k=0;k<8;k++) t+=red[k][lane];
        d_tw[b*DIM+j]=fmaxf(t+bias[j],0.f)*Wk[j]; }
}
__global__ void dense_m2(const float* __restrict__ W, const float* __restrict__ bias){
    int b=blockIdx.x, jc=blockIdx.y, w=threadIdx.x>>5, lane=threadIdx.x&31, j=jc*32+lane;
    __shared__ float sc[DIM], ss[DIM]; __shared__ float red[8][32];
    for (int d=threadIdx.x; d<DIM; d+=256){ sc[d]=d_cv[b*DIM+d]; ss[d]=d_subj[b*DIM+d]; }
    __syncthreads();
    float acc=0.f;
    if (j<DIM) for (int d=w; d<DIM; d+=8){
        acc = fmaf(sc[d], W[(size_t)d*DIM+j], acc);
        acc = fmaf(ss[d], W[(size_t)(DIM+d)*DIM+j] + W[(size_t)(2*DIM+d)*DIM+j], acc); }
    red[w][lane]=acc; __syncthreads();
    if (w==0 && j<DIM){ float t=0.f;
        #pragma unroll
        for (int k=0;k<8;k++) t+=red[k][lane];
        d_m[b*DIM+j]=fmaxf(t+bias[j],0.f); }
}
__device__ __forceinline__ float warpSum(float v){
    #pragma unroll
    for (int o=16;o;o>>=1) v += __shfl_xor_sync(0xffffffffu,v,o);
    return v;
}
__global__ void klogit_kernel(const float* __restrict__ Wk_b){
    int row = blockIdx.x, b = row>>10, tid = threadIdx.x;
    const __half* gr = g_h + (size_t)row*KP;
    const float* tw = d_tw + b*DIM;
    float s = 0.f;
    for (int d=tid; d<DIM; d+=128) s = fmaf(__half2float(gr[d]), tw[d], s);
    s = warpSum(s);
    __shared__ float sm[4];
    if ((tid&31)==0) sm[tid>>5]=s;
    __syncthreads();
    if (tid==0) d_klog[row]=sm[0]+sm[1]+sm[2]+sm[3]+Wk_b[0];
}
__global__ void softmax_k_kernel(){
    int b=blockIdx.x, tid=threadIdx.x;
    __shared__ float red[256];
    const float* kr = d_klog + b*TT;
    float lmax=-3.4e38f;
    for (int t=tid;t<TT;t+=256) lmax=fmaxf(lmax,kr[t]);
    red[tid]=lmax; __syncthreads();
    for (int s=128;s;s>>=1){ if(tid<s) red[tid]=fmaxf(red[tid],red[tid+s]); __syncthreads(); }
    float m=red[0]; __syncthreads();
    float ls=0.f;
    for (int t=tid;t<TT;t+=256) ls+=__expf(kr[t]-m);
    red[tid]=ls; __syncthreads();
    for (int s=128;s;s>>=1){ if(tid<s) red[tid]+=red[tid+s]; __syncthreads(); }
    float inv=1.f/red[0];
    for (int t=tid;t<TT;t+=256) d_kw[b*TT+t]=__expf(kr[t]-m)*inv;
}
__global__ void c_partial_kernel(){
    int b=blockIdx.x, ch=blockIdx.y, d=threadIdx.x; if (d>=DIM) return;
    float s=0.f;
    int base=b*TT+ch*32;
    for (int i=0;i<32;i++){ int row=base+i;
        s=fmaf(d_kw[row], __half2float(g_h[(size_t)row*KP+d]), s); }
    d_part[(b*32+ch)*DIM+d]=s;
}
__global__ void c_reduce_kernel(){
    int b=blockIdx.x, d=threadIdx.x; if (d>=DIM) return;
    float s=0.f;
    #pragma unroll
    for (int c=0;c<32;c++) s+=d_part[(b*32+c)*DIM+d];
    d_cv[b*DIM+d]=s;
}
__global__ void softmax_S_kernel(float* __restrict__ att){
    int row = blockIdx.x;
    int t = row & (TT-1);
    int tid = threadIdx.x;
    int w = tid>>5, lane = tid&31;
    __shared__ float srow[TT];
    __shared__ float red1[8]; __shared__ float red2[8];
    __shared__ float bc[2];
    __half2* Pr2 = reinterpret_cast<__half2*>(p_h + (size_t)row*TT);
    const float invs = 1.f/sqrtf(500.f);
    float s1=0.f, s2=0.f;
    for (int s=tid;s<TT/2;s+=256){
        float2 v = __half22float2(Pr2[s]);
        s1 += __expf(v.x) + __expf(v.y);
        float e0 = __expf(v.x*invs), e1 = __expf(v.y*invs);
        srow[2*s]=e0; srow[2*s+1]=e1;
        s2 += e0 + e1;
    }
    s1 = warpSum(s1); s2 = warpSum(s2);
    if (lane==0){ red1[w]=s1; red2[w]=s2; }
    __syncthreads();
    if (tid==0){
        float S1=0.f, S2=0.f;
        #pragma unroll
        for (int k=0;k<8;k++){ S1+=red1[k]; S2+=red2[k]; }
        bc[0]=S1; bc[1]=S2;
    }
    __syncthreads();
    float S1=bc[0], S2=bc[1];
    if (tid==0){
        float sd = __half2float(p_h[(size_t)row*TT+t]);
        att[row]=(1.f-__expf(sd)/S1)*invs;
    }
    float invZ2=1.f/S2;
    for (int s=tid;s<TT/2;s+=256)
        Pr2[s]=pack_h2(srow[2*s]*invZ2, srow[2*s+1]*invZ2);
}

// ---------------- streams ------------------------------------------------------------
struct StreamBundle {
    cudaStream_t s2;
    cudaEvent_t eFork0, eG, eJoin, eW;
    StreamBundle(){
        cudaStreamCreateWithFlags(&s2, cudaStreamNonBlocking);
        cudaEventCreateWithFlags(&eFork0, cudaEventDisableTiming);
        cudaEventCreateWithFlags(&eG,   cudaEventDisableTiming);
        cudaEventCreateWithFlags(&eJoin,cudaEventDisableTiming);
        cudaEventCreateWithFlags(&eW,   cudaEventDisableTiming);
    }
};
static StreamBundle g_sb;

// ---------------- launch -------------------------------------------------------------
extern "C" void kernel_launch(void* const* d_in, const int* in_sizes, int n_in,
                              void* d_out, int out_size)
{
    const int* words=(const int*)d_in[0];
    const int* pos=(const int*)d_in[2];
    const int* ner=(const int*)d_in[3];
    const int* subj_pos=(const int*)d_in[4];
    const int* obj_pos=(const int*)d_in[5];
    const int* chunks=(const int*)d_in[6];
    const int* on_path=(const int*)d_in[7];
    const float* dep_feat=(const float*)d_in[8];
    const float* emb_w=(const float*)d_in[9];
    const float* pos_w=(const float*)d_in[10];
    const float* ner_w=(const float*)d_in[11];
    const float* chunk_w=(const float*)d_in[12];
    const float* position_w=(const float*)d_in[13];
    const float* Wq_w=(const float*)d_in[14]; const float* Wq_b=(const float*)d_in[15];
    const float* Wc_w=(const float*)d_in[16]; const float* Wc_b=(const float*)d_in[17];
    const float* Wk_w=(const float*)d_in[18]; const float* Wk_b=(const float*)d_in[19];
    const float* Wm_w=(const float*)d_in[20]; const float* Wm_b=(const float*)d_in[21];
    const float* K_w=(const float*)d_in[22];  const float* K_b=(const float*)d_in[23];
    const float* Q_w=(const float*)d_in[24];  const float* Q_b=(const float*)d_in[25];
    const float* V_w=(const float*)d_in[26];  const float* V_b=(const float*)d_in[27];

    float* out = (float*)d_out;
    float* att = out + (size_t)NROWS*DIM;

    float *mp, *extp;
    __half *ghp,*tmpp,*kwp,*qwp,*mtp,*wthp,*vthp,*php;
    cudaGetSymbolAddress((void**)&mp, d_m);
    cudaGetSymbolAddress((void**)&extp, d_extT);
    cudaGetSymbolAddress((void**)&ghp, g_h);
    cudaGetSymbolAddress((void**)&tmpp, tmp_h);
    cudaGetSymbolAddress((void**)&kwp, kw_h);
    cudaGetSymbolAddress((void**)&qwp, qw_h);
    cudaGetSymbolAddress((void**)&mtp, mt_h);
    cudaGetSymbolAddress((void**)&wthp, wt_h);
    cudaGetSymbolAddress((void**)&vthp, vt_h);
    cudaGetSymbolAddress((void**)&php, p_h);

    cudaFuncSetAttribute(mm_gemm<3>, cudaFuncAttributeMaxDynamicSharedMemorySize, SMEM_DYN);
    cudaFuncSetAttribute(mm_gemm<5>, cudaFuncAttributeMaxDynamicSharedMemorySize, SMEM_DYN);
    cudaFuncSetAttribute(mm_gemm<6>, cudaFuncAttributeMaxDynamicSharedMemorySize, SMEM_DYN);
    cudaFuncSetAttribute(mm_projV,   cudaFuncAttributeMaxDynamicSharedMemorySize, SMEM_DYN);

    cudaStream_t s2 = g_sb.s2;

    // stream 0 head: Mt precompute chain (serial, ~7us) then embedding (R14 schedule)
    kwqw_copy<<<DIM, 512>>>(K_w, Q_w);
    mm_gemm<5><<<dim3(4,4,1), 256, SMEM_DYN>>>(qwp, 0, KP, kwp, 0, KP,
        nullptr, mtp, 0, KP, nullptr, 0, KP, 8);
    vecfast<<<dim3(64,2), 256>>>(K_w, Q_w, K_b, Q_b);

    // legal fork for s2 (event on origin stream after real nodes)
    cudaEventRecord(g_sb.eFork0, 0);
    cudaStreamWaitEvent(s2, g_sb.eFork0, 0);
    wtransV_kernel<<<dim3(16,16), dim3(32,8), 0, s2>>>(V_w);
    cudaEventRecord(g_sb.eW, s2);

    buildsplit_g_kernel<<<NROWS, 512>>>(words, pos, ner, chunks, subj_pos, obj_pos,
        on_path, dep_feat, emb_w, pos_w, ner_w, chunk_w, position_w);
    cudaEventRecord(g_sb.eG, 0);

    // side chain on s2 (consumes g_h, produces d_m)
    cudaStreamWaitEvent(s2, g_sb.eG, 0);
    subj_partial_kernel<<<dim3(BB,32), 512, 0, s2>>>(subj_pos);
    subj_reduce_kernel<<<BB, 512, 0, s2>>>();
    dense_q2<<<dim3(BB,16), 256, 0, s2>>>(Wq_w, Wq_b);
    dense_t2<<<dim3(BB,16), 256, 0, s2>>>(Wc_w, Wc_b, Wk_w);
    klogit_kernel<<<NROWS, 128, 0, s2>>>(Wk_b);
    softmax_k_kernel<<<BB, 256, 0, s2>>>();
    c_partial_kernel<<<dim3(BB,32), 512, 0, s2>>>();
    c_reduce_kernel<<<BB, 512, 0, s2>>>();
    dense_m2<<<dim3(BB,16), 256, 0, s2>>>(Wm_w, Wm_b);
    cudaEventRecord(g_sb.eJoin, s2);

    // stream 0: V projection (needs wtransV)
    cudaStreamWaitEvent(0, g_sb.eW, 0);
    mm_projV<<<dim3(4,128), 256, SMEM_DYN>>>(ghp, wthp, V_b, vthp);

    // tmp = g @ Mt^T + extT  (replaces K and Q projections)
    mm_gemm<6><<<dim3(4,128,1), 256, SMEM_DYN>>>(ghp, 0, KP, mtp, 0, KP,
        nullptr, tmpp, 0, KP, extp, 0, KP, 8);

    // S = tmp @ g^T -> fp16 into p_h
    mm_gemm<5><<<dim3(8,8,BB), 256, SMEM_DYN>>>(tmpp, (long)TT*KP, KP, ghp, (long)TT*KP, KP,
        nullptr, php, (long)TT*TT, TT, nullptr, 0, TT, 8);

    softmax_S_kernel<<<NROWS, 256>>>(att);

    // join + final GEMM: out = P @ vt^T, *m
    cudaStreamWaitEvent(0, g_sb.eJoin, 0);
    mm_gemm<3><<<dim3(4,8,BB), 256, SMEM_DYN>>>(php, (long)TT*TT, TT, vthp, (long)KP*TT, TT,
        out, nullptr, (long)TT*DIM, DIM, mp, DIM, DIM, 16);
}